// round 7
// baseline (speedup 1.0000x reference)
#include <cuda_runtime.h>
#include <math.h>

#define SDIM   256
#define MDIM   64

struct GConst {
    float k, logk, r, T1, T2, T3;
};

__device__ GConst g_c[2];
__device__ double g_sum = 0.0;
__device__ double g_acc[4] = {0.0, 0.0, 0.0, 0.0};
__device__ unsigned g_tick0 = 0;
__device__ unsigned g_tick1 = 0;

// ---------------------------------------------------------------------------
// Kernel 0: moderator sums + finalize (last block). 16 blocks x 128 threads.
// ---------------------------------------------------------------------------
__global__ void __launch_bounds__(128)
setup_kernel(const float* __restrict__ mod0,
             const float* __restrict__ mod1,
             const float* __restrict__ wm,
             const float* __restrict__ ods,
             int nstudy)
{
    __shared__ float swm[MDIM];
    const int tid = threadIdx.x;
    if (tid < MDIM) swm[tid] = wm[tid];
    __syncthreads();

    const int gid     = blockIdx.x * blockDim.x + tid;
    const int gstride = gridDim.x * blockDim.x;

    double m0 = 0.0, m20 = 0.0, m1 = 0.0, m21 = 0.0;
    for (int s = gid; s < nstudy; s += gstride) {
        const float4* r0 = (const float4*)(mod0 + (size_t)s * MDIM);
        const float4* r1 = (const float4*)(mod1 + (size_t)s * MDIM);
        float d0 = 0.f, d1 = 0.f;
        #pragma unroll
        for (int j = 0; j < MDIM / 4; ++j) {
            float4 a = r0[j], b = r1[j];
            const float4 w = ((const float4*)swm)[j];
            d0 += a.x*w.x + a.y*w.y + a.z*w.z + a.w*w.w;
            d1 += b.x*w.x + b.y*w.y + b.z*w.z + b.w*w.w;
        }
        float e0 = expf(d0), e1 = expf(d1);
        m0  += (double)e0;  m20 += (double)e0 * (double)e0;
        m1  += (double)e1;  m21 += (double)e1 * (double)e1;
    }

    #pragma unroll
    for (int off = 16; off > 0; off >>= 1) {
        m0  += __shfl_xor_sync(0xffffffff, m0,  off);
        m20 += __shfl_xor_sync(0xffffffff, m20, off);
        m1  += __shfl_xor_sync(0xffffffff, m1,  off);
        m21 += __shfl_xor_sync(0xffffffff, m21, off);
    }
    if ((tid & 31) == 0) {
        atomicAdd(&g_acc[0], m0);
        atomicAdd(&g_acc[1], m20);
        atomicAdd(&g_acc[2], m1);
        atomicAdd(&g_acc[3], m21);
    }
    __threadfence();
    __syncthreads();

    if (tid == 0) {
        unsigned t = atomicAdd(&g_tick0, 1u);
        if (t == gridDim.x - 1) {
            __threadfence();
            double sm[2], sm2[2];
            sm[0]  = atomicAdd(&g_acc[0], 0.0);
            sm2[0] = atomicAdd(&g_acc[1], 0.0);
            sm[1]  = atomicAdd(&g_acc[2], 0.0);
            sm2[1] = atomicAdd(&g_acc[3], 0.0);
            #pragma unroll
            for (int g = 0; g < 2; ++g) {
                float  so = ods[g];
                double vv = 1.0 / ((double)so * (double)so);
                double r  = vv * sm[g] * sm[g] / sm2[g];
                double k  = sm2[g] / (vv * sm[g]);
                float rf = (float)r;
                float T1 = logf(rf);
                float T2 = T1 + logf(rf + 1.0f) - 0.6931471805599453f;
                float T3 = T2 + logf(rf + 2.0f) - 1.0986122886681098f;
                g_c[g].k = (float)k;
                g_c[g].logk = logf((float)k);
                g_c[g].r = rf;
                g_c[g].T1 = T1;
                g_c[g].T2 = T2;
                g_c[g].T3 = T3;
            }
            g_sum = 0.0;
            g_acc[0] = 0.0; g_acc[1] = 0.0; g_acc[2] = 0.0; g_acc[3] = 0.0;
            g_tick0 = 0;
            __threadfence();
        }
    }
}

__device__ __forceinline__ float group_term(float k, float logk, float r,
                                            float T1, float T2, float T3,
                                            float dot, float y)
{
    float t  = k * __expf(dot);
    float l1 = log1pf(t);
    int iy = (int)y;
    float T = (iy == 1) ? T1 : (iy == 2) ? T2 : (iy == 3) ? T3 : 0.0f;
    return fmaf(-(r + y), l1, fmaf(y, logk + dot, T));
}

// Non-hoistable LDS.128 (volatile asm so ptxas re-loads each iteration
// instead of pinning 16 weight registers across the loop body).
__device__ __forceinline__ float4 lds128(unsigned addr)
{
    float4 v;
    asm volatile("ld.shared.v4.f32 {%0,%1,%2,%3}, [%4];"
                 : "=f"(v.x), "=f"(v.y), "=f"(v.z), "=f"(v.w) : "r"(addr));
    return v;
}

__device__ __forceinline__ float dot8(const float4 a, const float4 b,
                                      const float4 wa, const float4 wb)
{
    return a.x*wa.x + a.y*wa.y + a.z*wa.z + a.w*wa.w
         + b.x*wb.x + b.y*wb.y + b.z*wb.z + b.w*wb.w;
}

// Merge two per-lane values across the 'o' butterfly.
__device__ __forceinline__ float merge_pair(float A, float B, int o)
{
    float send = (threadIdx.x & o) ? A : B;
    float keep = (threadIdx.x & o) ? B : A;
    return keep + __shfl_xor_sync(0xffffffff, send, o);
}

// ---------------------------------------------------------------------------
// Kernel 1: streaming. 4 contiguous voxels per warp-iter, weights in smem,
// 5 blocks/SM (<=51 regs). Grid = 740 = one full wave.
// ---------------------------------------------------------------------------
__global__ void __launch_bounds__(256, 5)
nb_main_kernel(const float* __restrict__ X,
               const float* __restrict__ y0,
               const float* __restrict__ y1,
               const float* __restrict__ W,
               float* __restrict__ out,
               int V)
{
    const int tid  = threadIdx.x;
    const int lane = tid & 31;
    const int widb = tid >> 5;

    __shared__ float4 sW[128];       // [2,256] floats = 128 float4
    __shared__ double sred[8];
    if (tid < 128) sW[tid] = ((const float4*)W)[tid];
    __syncthreads();

    const unsigned swb = (unsigned)__cvta_generic_to_shared(sW);
    const unsigned aw0a = swb + (unsigned)(lane)        * 16u;
    const unsigned aw0b = swb + (unsigned)(lane + 32)   * 16u;
    const unsigned aw1a = swb + (unsigned)(lane + 64)   * 16u;
    const unsigned aw1b = swb + (unsigned)(lane + 96)   * 16u;

    const GConst c0 = g_c[0];
    const GConst c1 = g_c[1];
    const bool odd = (lane & 1);
    const float sk    = odd ? c1.k    : c0.k;
    const float slogk = odd ? c1.logk : c0.logk;
    const float sr    = odd ? c1.r    : c0.r;
    const float sT1   = odd ? c1.T1   : c0.T1;
    const float sT2   = odd ? c1.T2   : c0.T2;
    const float sT3   = odd ? c1.T3   : c0.T3;
    const float* yp   = odd ? y1 : y0;

    const int nwb    = blockDim.x >> 5;
    const int gwarp  = blockIdx.x * nwb + widb;
    const int nwarps = gridDim.x * nwb;

    double acc = 0.0;

    const int ngroups = (V + 3) >> 2;
    for (int g = gwarp; g < ngroups; g += nwarps) {
        const int v = g << 2;
        const int r1 = min(v + 1, V - 1);
        const int r2 = min(v + 2, V - 1);
        const int r3 = min(v + 3, V - 1);
        const float4* x0 = (const float4*)(X + (size_t)v  * SDIM);
        const float4* x1 = (const float4*)(X + (size_t)r1 * SDIM);
        const float4* x2 = (const float4*)(X + (size_t)r2 * SDIM);
        const float4* x3 = (const float4*)(X + (size_t)r3 * SDIM);

        // front-batched 8x LDG.128 (MLP)
        float4 a0 = __ldcs(x0 + lane), b0 = __ldcs(x0 + lane + 32);
        float4 a1 = __ldcs(x1 + lane), b1 = __ldcs(x1 + lane + 32);
        float4 a2 = __ldcs(x2 + lane), b2 = __ldcs(x2 + lane + 32);
        float4 a3 = __ldcs(x3 + lane), b3 = __ldcs(x3 + lane + 32);

        float ylv = 0.f;
        if (lane < 8) {
            int idx = v + (lane >> 1);
            if (idx < V) ylv = yp[idx];
        }

        // group-0 weights, 4 dots, then group-1 weights (8 weight regs live)
        float4 wa = lds128(aw0a), wb = lds128(aw0b);
        float p0 = dot8(a0, b0, wa, wb);
        float p1 = dot8(a1, b1, wa, wb);
        float p2 = dot8(a2, b2, wa, wb);
        float p3 = dot8(a3, b3, wa, wb);
        wa = lds128(aw1a); wb = lds128(aw1b);
        float q0 = dot8(a0, b0, wa, wb);
        float q1 = dot8(a1, b1, wa, wb);
        float q2 = dot8(a2, b2, wa, wb);
        float q3 = dot8(a3, b3, wa, wb);

        // merge tree: 8 values -> lane slots (group = lane&1, row = (lane>>1)&3)
        float e0 = merge_pair(p0, q0, 1);
        float e1 = merge_pair(p1, q1, 1);
        float e2 = merge_pair(p2, q2, 1);
        float e3 = merge_pair(p3, q3, 1);
        float f0 = merge_pair(e0, e1, 2);
        float f1 = merge_pair(e2, e3, 2);
        float gg = merge_pair(f0, f1, 4);
        gg += __shfl_xor_sync(0xffffffff, gg, 8);
        gg += __shfl_xor_sync(0xffffffff, gg, 16);

        float term = 0.f;
        if (lane < 8 && (v + (lane >> 1)) < V)
            term = group_term(sk, slogk, sr, sT1, sT2, sT3, gg, ylv);

        term += __shfl_xor_sync(0xffffffff, term, 1);
        term += __shfl_xor_sync(0xffffffff, term, 2);
        term += __shfl_xor_sync(0xffffffff, term, 4);
        if (lane == 0) acc += (double)term;
    }

    if (lane == 0) sred[widb] = acc;
    __syncthreads();
    if (tid == 0) {
        double t = 0.0;
        for (int i = 0; i < nwb; ++i) t += sred[i];
        atomicAdd(&g_sum, t);
        __threadfence();
        unsigned tk = atomicAdd(&g_tick1, 1u);
        if (tk == gridDim.x - 1) {
            __threadfence();
            double total = atomicAdd(&g_sum, 0.0);
            out[0] = (float)(-total);
            g_tick1 = 0;
            __threadfence();
        }
    }
}

extern "C" void kernel_launch(void* const* d_in, const int* in_sizes, int n_in,
                              void* d_out, int out_size)
{
    const float* X    = (const float*)d_in[0];
    const float* mod0 = (const float*)d_in[1];
    const float* mod1 = (const float*)d_in[2];
    const float* y0   = (const float*)d_in[3];
    const float* y1   = (const float*)d_in[4];
    const float* W    = (const float*)d_in[5];
    const float* wm   = (const float*)d_in[6];
    const float* ods  = (const float*)d_in[7];
    float* out = (float*)d_out;

    const int V = in_sizes[0] / SDIM;
    const int S = in_sizes[1] / MDIM;

    setup_kernel<<<16, 128>>>(mod0, mod1, wm, ods, S);
    nb_main_kernel<<<740, 256>>>(X, y0, y1, W, out, V);
}

// round 8
// speedup vs baseline: 1.0238x; 1.0238x over previous
#include <cuda_runtime.h>
#include <math.h>

#define SDIM   256
#define MDIM   64

struct GConst {
    float k, logk, r, T1, T2, T3;
};

__device__ GConst g_c[2];
__device__ double g_sum = 0.0;
__device__ double g_acc[4] = {0.0, 0.0, 0.0, 0.0};
__device__ unsigned g_tick0 = 0;
__device__ unsigned g_tick1 = 0;

// ---------------------------------------------------------------------------
// Kernel 0: moderator sums + finalize. 8 blocks x 256, one study per thread.
// ---------------------------------------------------------------------------
__global__ void __launch_bounds__(256)
setup_kernel(const float* __restrict__ mod0,
             const float* __restrict__ mod1,
             const float* __restrict__ wm,
             const float* __restrict__ ods,
             int nstudy)
{
    __shared__ float swm[MDIM];
    const int tid = threadIdx.x;
    if (tid < MDIM) swm[tid] = wm[tid];
    __syncthreads();

    const int s = blockIdx.x * 256 + tid;   // one study per thread
    double m0 = 0.0, m20 = 0.0, m1 = 0.0, m21 = 0.0;
    if (s < nstudy) {
        const float4* r0 = (const float4*)(mod0 + (size_t)s * MDIM);
        const float4* r1 = (const float4*)(mod1 + (size_t)s * MDIM);
        float d0 = 0.f, d1 = 0.f;
        #pragma unroll
        for (int j = 0; j < MDIM / 4; ++j) {
            float4 a = r0[j], b = r1[j];
            const float4 w = ((const float4*)swm)[j];
            d0 += a.x*w.x + a.y*w.y + a.z*w.z + a.w*w.w;
            d1 += b.x*w.x + b.y*w.y + b.z*w.z + b.w*w.w;
        }
        float e0 = expf(d0), e1 = expf(d1);
        m0  = (double)e0;  m20 = (double)e0 * (double)e0;
        m1  = (double)e1;  m21 = (double)e1 * (double)e1;
    }

    #pragma unroll
    for (int off = 16; off > 0; off >>= 1) {
        m0  += __shfl_xor_sync(0xffffffff, m0,  off);
        m20 += __shfl_xor_sync(0xffffffff, m20, off);
        m1  += __shfl_xor_sync(0xffffffff, m1,  off);
        m21 += __shfl_xor_sync(0xffffffff, m21, off);
    }
    if ((tid & 31) == 0) {
        atomicAdd(&g_acc[0], m0);
        atomicAdd(&g_acc[1], m20);
        atomicAdd(&g_acc[2], m1);
        atomicAdd(&g_acc[3], m21);
    }
    __threadfence();
    __syncthreads();

    if (tid == 0) {
        unsigned t = atomicAdd(&g_tick0, 1u);
        if (t == gridDim.x - 1) {
            __threadfence();
            double sm[2], sm2[2];
            sm[0]  = atomicAdd(&g_acc[0], 0.0);
            sm2[0] = atomicAdd(&g_acc[1], 0.0);
            sm[1]  = atomicAdd(&g_acc[2], 0.0);
            sm2[1] = atomicAdd(&g_acc[3], 0.0);
            #pragma unroll
            for (int g = 0; g < 2; ++g) {
                float  so = ods[g];
                double vv = 1.0 / ((double)so * (double)so);
                double r  = vv * sm[g] * sm[g] / sm2[g];
                double k  = sm2[g] / (vv * sm[g]);
                float rf = (float)r;
                float T1 = logf(rf);
                float T2 = T1 + logf(rf + 1.0f) - 0.6931471805599453f;
                float T3 = T2 + logf(rf + 2.0f) - 1.0986122886681098f;
                g_c[g].k = (float)k;
                g_c[g].logk = logf((float)k);
                g_c[g].r = rf;
                g_c[g].T1 = T1;
                g_c[g].T2 = T2;
                g_c[g].T3 = T3;
            }
            g_sum = 0.0;
            g_acc[0] = 0.0; g_acc[1] = 0.0; g_acc[2] = 0.0; g_acc[3] = 0.0;
            g_tick0 = 0;
            __threadfence();
        }
    }
}

__device__ __forceinline__ float group_term(float k, float logk, float r,
                                            float T1, float T2, float T3,
                                            float dot, float y)
{
    float t  = k * __expf(dot);
    float l1 = log1pf(t);
    int iy = (int)y;
    float T = (iy == 1) ? T1 : (iy == 2) ? T2 : (iy == 3) ? T3 : 0.0f;
    return fmaf(-(r + y), l1, fmaf(y, logk + dot, T));
}

__device__ __forceinline__ float2 dots_for_row(const float4 a, const float4 b,
                                               const float4 w0a, const float4 w0b,
                                               const float4 w1a, const float4 w1b)
{
    float p0 = a.x*w0a.x + a.y*w0a.y + a.z*w0a.z + a.w*w0a.w
             + b.x*w0b.x + b.y*w0b.y + b.z*w0b.z + b.w*w0b.w;
    float p1 = a.x*w1a.x + a.y*w1a.y + a.z*w1a.z + a.w*w1a.w
             + b.x*w1b.x + b.y*w1b.y + b.z*w1b.z + b.w*w1b.w;
    return make_float2(p0, p1);
}

__device__ __forceinline__ float merge_pair(float A, float B, int o)
{
    float send = (threadIdx.x & o) ? A : B;
    float keep = (threadIdx.x & o) ? B : A;
    return keep + __shfl_xor_sync(0xffffffff, send, o);
}

// ---------------------------------------------------------------------------
// Kernel 1: streaming (R5 configuration, proven 81.4us @ 80.6% DRAM).
// Warp handles contiguous groups of 4 voxels; weights in registers;
// merge-tree reduction; distributed epilogue; 64 regs, 4 blocks/SM.
// ---------------------------------------------------------------------------
__global__ void __launch_bounds__(256, 4)
nb_main_kernel(const float* __restrict__ X,
               const float* __restrict__ y0,
               const float* __restrict__ y1,
               const float* __restrict__ W,
               float* __restrict__ out,
               int V)
{
    const int lane   = threadIdx.x & 31;
    const int widb   = threadIdx.x >> 5;
    const int nwb    = blockDim.x >> 5;
    const int gwarp  = blockIdx.x * nwb + widb;
    const int nwarps = gridDim.x * nwb;

    const float4* W4 = (const float4*)W;
    const float4 w0a = W4[lane],      w0b = W4[lane + 32];
    const float4 w1a = W4[64 + lane], w1b = W4[96 + lane];

    const GConst c0 = g_c[0];
    const GConst c1 = g_c[1];
    const bool odd = (lane & 1);
    const float sk    = odd ? c1.k    : c0.k;
    const float slogk = odd ? c1.logk : c0.logk;
    const float sr    = odd ? c1.r    : c0.r;
    const float sT1   = odd ? c1.T1   : c0.T1;
    const float sT2   = odd ? c1.T2   : c0.T2;
    const float sT3   = odd ? c1.T3   : c0.T3;
    const float* yp   = odd ? y1 : y0;

    double acc = 0.0;

    const int ngroups = (V + 3) >> 2;
    for (int g = gwarp; g < ngroups; g += nwarps) {
        const int v = g << 2;
        const int r1 = min(v + 1, V - 1);
        const int r2 = min(v + 2, V - 1);
        const int r3 = min(v + 3, V - 1);
        const float4* x0 = (const float4*)(X + (size_t)v  * SDIM);
        const float4* x1 = (const float4*)(X + (size_t)r1 * SDIM);
        const float4* x2 = (const float4*)(X + (size_t)r2 * SDIM);
        const float4* x3 = (const float4*)(X + (size_t)r3 * SDIM);

        float4 a0 = __ldcs(x0 + lane), b0 = __ldcs(x0 + lane + 32);
        float4 a1 = __ldcs(x1 + lane), b1 = __ldcs(x1 + lane + 32);
        float4 a2 = __ldcs(x2 + lane), b2 = __ldcs(x2 + lane + 32);
        float4 a3 = __ldcs(x3 + lane), b3 = __ldcs(x3 + lane + 32);

        float ylv = 0.f;
        if (lane < 8) {
            int idx = v + (lane >> 1);
            if (idx < V) ylv = __ldcs(yp + idx);
        }

        float2 d0 = dots_for_row(a0, b0, w0a, w0b, w1a, w1b);
        float2 d1 = dots_for_row(a1, b1, w0a, w0b, w1a, w1b);
        float2 d2 = dots_for_row(a2, b2, w0a, w0b, w1a, w1b);
        float2 d3 = dots_for_row(a3, b3, w0a, w0b, w1a, w1b);

        float e0 = merge_pair(d0.x, d0.y, 1);
        float e1 = merge_pair(d1.x, d1.y, 1);
        float e2 = merge_pair(d2.x, d2.y, 1);
        float e3 = merge_pair(d3.x, d3.y, 1);
        float f0 = merge_pair(e0, e1, 2);
        float f1 = merge_pair(e2, e3, 2);
        float gg = merge_pair(f0, f1, 4);
        gg += __shfl_xor_sync(0xffffffff, gg, 8);
        gg += __shfl_xor_sync(0xffffffff, gg, 16);

        float term = 0.f;
        if (lane < 8 && (v + (lane >> 1)) < V)
            term = group_term(sk, slogk, sr, sT1, sT2, sT3, gg, ylv);

        term += __shfl_xor_sync(0xffffffff, term, 1);
        term += __shfl_xor_sync(0xffffffff, term, 2);
        term += __shfl_xor_sync(0xffffffff, term, 4);
        if (lane == 0) acc += (double)term;
    }

    __shared__ double sred[8];
    if (lane == 0) sred[widb] = acc;
    __syncthreads();
    if (threadIdx.x == 0) {
        double t = 0.0;
        for (int i = 0; i < nwb; ++i) t += sred[i];
        atomicAdd(&g_sum, t);
        __threadfence();
        unsigned tk = atomicAdd(&g_tick1, 1u);
        if (tk == gridDim.x - 1) {
            __threadfence();
            double total = atomicAdd(&g_sum, 0.0);
            out[0] = (float)(-total);
            g_tick1 = 0;
            __threadfence();
        }
    }
}

extern "C" void kernel_launch(void* const* d_in, const int* in_sizes, int n_in,
                              void* d_out, int out_size)
{
    const float* X    = (const float*)d_in[0];
    const float* mod0 = (const float*)d_in[1];
    const float* mod1 = (const float*)d_in[2];
    const float* y0   = (const float*)d_in[3];
    const float* y1   = (const float*)d_in[4];
    const float* W    = (const float*)d_in[5];
    const float* wm   = (const float*)d_in[6];
    const float* ods  = (const float*)d_in[7];
    float* out = (float*)d_out;

    const int V = in_sizes[0] / SDIM;
    const int S = in_sizes[1] / MDIM;

    setup_kernel<<<8, 256>>>(mod0, mod1, wm, ods, S);
    nb_main_kernel<<<1184, 256>>>(X, y0, y1, W, out, V);
}

// round 9
// speedup vs baseline: 1.0799x; 1.0549x over previous
#include <cuda_runtime.h>
#include <math.h>

#define SDIM   256
#define MDIM   64

struct GConst {
    float k, logk, r, T1, T2, T3;
};

__device__ GConst g_c[2];
__device__ double g_sum = 0.0;
__device__ double g_acc[4] = {0.0, 0.0, 0.0, 0.0};
__device__ unsigned g_tick0 = 0;
__device__ unsigned g_tick1 = 0;

// ---------------------------------------------------------------------------
// Kernel 0: moderator sums + finalize. 16 blocks x 128 (measured-best shape).
// ---------------------------------------------------------------------------
__global__ void __launch_bounds__(128)
setup_kernel(const float* __restrict__ mod0,
             const float* __restrict__ mod1,
             const float* __restrict__ wm,
             const float* __restrict__ ods,
             int nstudy)
{
    __shared__ float swm[MDIM];
    const int tid = threadIdx.x;
    if (tid < MDIM) swm[tid] = wm[tid];
    __syncthreads();

    const int gid     = blockIdx.x * blockDim.x + tid;
    const int gstride = gridDim.x * blockDim.x;

    double m0 = 0.0, m20 = 0.0, m1 = 0.0, m21 = 0.0;
    for (int s = gid; s < nstudy; s += gstride) {
        const float4* r0 = (const float4*)(mod0 + (size_t)s * MDIM);
        const float4* r1 = (const float4*)(mod1 + (size_t)s * MDIM);
        float d0 = 0.f, d1 = 0.f;
        #pragma unroll
        for (int j = 0; j < MDIM / 4; ++j) {
            float4 a = r0[j], b = r1[j];
            const float4 w = ((const float4*)swm)[j];
            d0 += a.x*w.x + a.y*w.y + a.z*w.z + a.w*w.w;
            d1 += b.x*w.x + b.y*w.y + b.z*w.z + b.w*w.w;
        }
        float e0 = expf(d0), e1 = expf(d1);
        m0  += (double)e0;  m20 += (double)e0 * (double)e0;
        m1  += (double)e1;  m21 += (double)e1 * (double)e1;
    }

    #pragma unroll
    for (int off = 16; off > 0; off >>= 1) {
        m0  += __shfl_xor_sync(0xffffffff, m0,  off);
        m20 += __shfl_xor_sync(0xffffffff, m20, off);
        m1  += __shfl_xor_sync(0xffffffff, m1,  off);
        m21 += __shfl_xor_sync(0xffffffff, m21, off);
    }
    if ((tid & 31) == 0) {
        atomicAdd(&g_acc[0], m0);
        atomicAdd(&g_acc[1], m20);
        atomicAdd(&g_acc[2], m1);
        atomicAdd(&g_acc[3], m21);
    }
    __threadfence();
    __syncthreads();

    if (tid == 0) {
        unsigned t = atomicAdd(&g_tick0, 1u);
        if (t == gridDim.x - 1) {
            __threadfence();
            double sm[2], sm2[2];
            sm[0]  = atomicAdd(&g_acc[0], 0.0);
            sm2[0] = atomicAdd(&g_acc[1], 0.0);
            sm[1]  = atomicAdd(&g_acc[2], 0.0);
            sm2[1] = atomicAdd(&g_acc[3], 0.0);
            #pragma unroll
            for (int g = 0; g < 2; ++g) {
                float  so = ods[g];
                double vv = 1.0 / ((double)so * (double)so);
                double r  = vv * sm[g] * sm[g] / sm2[g];
                double k  = sm2[g] / (vv * sm[g]);
                float rf = (float)r;
                float T1 = logf(rf);
                float T2 = T1 + logf(rf + 1.0f) - 0.6931471805599453f;
                float T3 = T2 + logf(rf + 2.0f) - 1.0986122886681098f;
                g_c[g].k = (float)k;
                g_c[g].logk = logf((float)k);
                g_c[g].r = rf;
                g_c[g].T1 = T1;
                g_c[g].T2 = T2;
                g_c[g].T3 = T3;
            }
            g_sum = 0.0;
            g_acc[0] = 0.0; g_acc[1] = 0.0; g_acc[2] = 0.0; g_acc[3] = 0.0;
            g_tick0 = 0;
            __threadfence();
        }
    }
}

__device__ __forceinline__ float group_term(float k, float logk, float r,
                                            float T1, float T2, float T3,
                                            float dot, float y)
{
    float t  = k * __expf(dot);
    float l1 = log1pf(t);
    int iy = (int)y;
    float T = (iy == 1) ? T1 : (iy == 2) ? T2 : (iy == 3) ? T3 : 0.0f;
    return fmaf(-(r + y), l1, fmaf(y, logk + dot, T));
}

__device__ __forceinline__ float2 dots_for_row(const float4 a, const float4 b,
                                               const float4 w0a, const float4 w0b,
                                               const float4 w1a, const float4 w1b)
{
    float p0 = a.x*w0a.x + a.y*w0a.y + a.z*w0a.z + a.w*w0a.w
             + b.x*w0b.x + b.y*w0b.y + b.z*w0b.z + b.w*w0b.w;
    float p1 = a.x*w1a.x + a.y*w1a.y + a.z*w1a.z + a.w*w1a.w
             + b.x*w1b.x + b.y*w1b.y + b.z*w1b.z + b.w*w1b.w;
    return make_float2(p0, p1);
}

__device__ __forceinline__ float merge_pair(float A, float B, int o)
{
    float send = (threadIdx.x & o) ? A : B;
    float keep = (threadIdx.x & o) ? B : A;
    return keep + __shfl_xor_sync(0xffffffff, send, o);
}

// ---------------------------------------------------------------------------
// Kernel 1: streaming (R5 loop body verbatim). Grid = 592: one fully
// resident wave at 4 blocks/SM; grid-stride covers all voxel groups.
// ---------------------------------------------------------------------------
__global__ void __launch_bounds__(256, 4)
nb_main_kernel(const float* __restrict__ X,
               const float* __restrict__ y0,
               const float* __restrict__ y1,
               const float* __restrict__ W,
               float* __restrict__ out,
               int V)
{
    const int lane   = threadIdx.x & 31;
    const int widb   = threadIdx.x >> 5;
    const int nwb    = blockDim.x >> 5;
    const int gwarp  = blockIdx.x * nwb + widb;
    const int nwarps = gridDim.x * nwb;

    const float4* W4 = (const float4*)W;
    const float4 w0a = W4[lane],      w0b = W4[lane + 32];
    const float4 w1a = W4[64 + lane], w1b = W4[96 + lane];

    const GConst c0 = g_c[0];
    const GConst c1 = g_c[1];
    const bool odd = (lane & 1);
    const float sk    = odd ? c1.k    : c0.k;
    const float slogk = odd ? c1.logk : c0.logk;
    const float sr    = odd ? c1.r    : c0.r;
    const float sT1   = odd ? c1.T1   : c0.T1;
    const float sT2   = odd ? c1.T2   : c0.T2;
    const float sT3   = odd ? c1.T3   : c0.T3;
    const float* yp   = odd ? y1 : y0;

    double acc = 0.0;

    const int ngroups = (V + 3) >> 2;
    for (int g = gwarp; g < ngroups; g += nwarps) {
        const int v = g << 2;
        const int r1 = min(v + 1, V - 1);
        const int r2 = min(v + 2, V - 1);
        const int r3 = min(v + 3, V - 1);
        const float4* x0 = (const float4*)(X + (size_t)v  * SDIM);
        const float4* x1 = (const float4*)(X + (size_t)r1 * SDIM);
        const float4* x2 = (const float4*)(X + (size_t)r2 * SDIM);
        const float4* x3 = (const float4*)(X + (size_t)r3 * SDIM);

        float4 a0 = __ldcs(x0 + lane), b0 = __ldcs(x0 + lane + 32);
        float4 a1 = __ldcs(x1 + lane), b1 = __ldcs(x1 + lane + 32);
        float4 a2 = __ldcs(x2 + lane), b2 = __ldcs(x2 + lane + 32);
        float4 a3 = __ldcs(x3 + lane), b3 = __ldcs(x3 + lane + 32);

        float ylv = 0.f;
        if (lane < 8) {
            int idx = v + (lane >> 1);
            if (idx < V) ylv = __ldcs(yp + idx);
        }

        float2 d0 = dots_for_row(a0, b0, w0a, w0b, w1a, w1b);
        float2 d1 = dots_for_row(a1, b1, w0a, w0b, w1a, w1b);
        float2 d2 = dots_for_row(a2, b2, w0a, w0b, w1a, w1b);
        float2 d3 = dots_for_row(a3, b3, w0a, w0b, w1a, w1b);

        float e0 = merge_pair(d0.x, d0.y, 1);
        float e1 = merge_pair(d1.x, d1.y, 1);
        float e2 = merge_pair(d2.x, d2.y, 1);
        float e3 = merge_pair(d3.x, d3.y, 1);
        float f0 = merge_pair(e0, e1, 2);
        float f1 = merge_pair(e2, e3, 2);
        float gg = merge_pair(f0, f1, 4);
        gg += __shfl_xor_sync(0xffffffff, gg, 8);
        gg += __shfl_xor_sync(0xffffffff, gg, 16);

        float term = 0.f;
        if (lane < 8 && (v + (lane >> 1)) < V)
            term = group_term(sk, slogk, sr, sT1, sT2, sT3, gg, ylv);

        term += __shfl_xor_sync(0xffffffff, term, 1);
        term += __shfl_xor_sync(0xffffffff, term, 2);
        term += __shfl_xor_sync(0xffffffff, term, 4);
        if (lane == 0) acc += (double)term;
    }

    __shared__ double sred[8];
    if (lane == 0) sred[widb] = acc;
    __syncthreads();
    if (threadIdx.x == 0) {
        double t = 0.0;
        for (int i = 0; i < nwb; ++i) t += sred[i];
        atomicAdd(&g_sum, t);
        __threadfence();
        unsigned tk = atomicAdd(&g_tick1, 1u);
        if (tk == gridDim.x - 1) {
            __threadfence();
            double total = atomicAdd(&g_sum, 0.0);
            out[0] = (float)(-total);
            g_tick1 = 0;
            __threadfence();
        }
    }
}

extern "C" void kernel_launch(void* const* d_in, const int* in_sizes, int n_in,
                              void* d_out, int out_size)
{
    const float* X    = (const float*)d_in[0];
    const float* mod0 = (const float*)d_in[1];
    const float* mod1 = (const float*)d_in[2];
    const float* y0   = (const float*)d_in[3];
    const float* y1   = (const float*)d_in[4];
    const float* W    = (const float*)d_in[5];
    const float* wm   = (const float*)d_in[6];
    const float* ods  = (const float*)d_in[7];
    float* out = (float*)d_out;

    const int V = in_sizes[0] / SDIM;
    const int S = in_sizes[1] / MDIM;

    setup_kernel<<<16, 128>>>(mod0, mod1, wm, ods, S);
    nb_main_kernel<<<592, 256>>>(X, y0, y1, W, out, V);
}